// round 1
// baseline (speedup 1.0000x reference)
#include <cuda_runtime.h>
#include <math.h>

// Shapes (fixed by the problem)
// T=64, B=1, C=768, V=H*W*D=512, heads=12, hd=64, 3C=2304, M = T*V = 32768

__device__ float g_scale[64 * 768];
__device__ float g_shift[64 * 768];
__device__ float g_bias[12 * 64 * 64];
__device__ float g_q[512 * 12 * 64 * 64];
__device__ float g_k[512 * 12 * 64 * 64];
__device__ float g_v[512 * 12 * 64 * 64];
__device__ float g_o[32768 * 768];

// ---------------------------------------------------------------------------
// 1) GroupNorm statistics -> fused per-(t,c) scale/shift
//    xn[t,c,v] = x*scale[t,c] + shift[t,c]
// ---------------------------------------------------------------------------
__global__ void gn_stats_kernel(const float* __restrict__ x,
                                const float* __restrict__ w) {
    const int t = blockIdx.x / 12;
    const int g = blockIdx.x % 12;
    const float* base = x + (size_t)t * 768 * 512 + (size_t)g * 64 * 512;

    float s = 0.f, s2 = 0.f;
    for (int i = threadIdx.x * 4; i < 32768; i += 256 * 4) {
        float4 a = *(const float4*)(base + i);
        s  += a.x + a.y + a.z + a.w;
        s2 += a.x * a.x + a.y * a.y + a.z * a.z + a.w * a.w;
    }
    __shared__ float red[256];
    __shared__ float red2[256];
    red[threadIdx.x] = s;
    red2[threadIdx.x] = s2;
    __syncthreads();
    for (int o = 128; o > 0; o >>= 1) {
        if (threadIdx.x < o) {
            red[threadIdx.x]  += red[threadIdx.x + o];
            red2[threadIdx.x] += red2[threadIdx.x + o];
        }
        __syncthreads();
    }
    __shared__ float smu, sinv;
    if (threadIdx.x == 0) {
        float mu  = red[0] * (1.f / 32768.f);
        float var = red2[0] * (1.f / 32768.f) - mu * mu;
        smu  = mu;
        sinv = rsqrtf(var + 1e-5f);
    }
    __syncthreads();
    if (threadIdx.x < 64) {
        int c = g * 64 + threadIdx.x;
        float sc = sinv * w[c];
        g_scale[t * 768 + c] = sc;
        g_shift[t * 768 + c] = -smu * sc;
    }
}

// ---------------------------------------------------------------------------
// 2) T5 relative-position bias table: g_bias[he][t][s]
// ---------------------------------------------------------------------------
__global__ void bias_kernel(const float* __restrict__ emb) {
    const int t = blockIdx.x;
    const int s = threadIdx.x;
    int rel = t - s;                  // ctx - mem
    int ret = rel < 0 ? 16 : 0;
    int n = rel < 0 ? -rel : rel;
    int b;
    if (n < 8) {
        b = n;
    } else {
        float f = logf((float)n / 8.0f);
        f = f / 2.772588722239781f;   // log(128/8)
        f = f * 8.0f;
        b = 8 + (int)f;
        if (b > 15) b = 15;
    }
    int bucket = ret + b;
    #pragma unroll
    for (int he = 0; he < 12; he++)
        g_bias[he * 4096 + t * 64 + s] = emb[bucket * 12 + he];
}

// ---------------------------------------------------------------------------
// 3) GEMM1: qkv[n,o] = sum_c xn[n,c] * w_in[o,c] + b_in[o]
//    A is read directly from x (layout t,c,v) with on-the-fly normalization.
//    Epilogue scatters to q/k/v in layout [(v*12+he)*64+t][64].
// ---------------------------------------------------------------------------
__global__ void __launch_bounds__(256) gemm_qkv_kernel(
        const float* __restrict__ x,
        const float* __restrict__ w_in,
        const float* __restrict__ b_in) {
    __shared__ float As[16 * 128];
    __shared__ float Bs[16 * 128];
    const int tid = threadIdx.x;
    const int tx = tid & 15, ty = tid >> 4;
    const int n0 = blockIdx.y * 128;
    const int o0 = blockIdx.x * 128;
    const int t  = n0 >> 9;
    const int v0 = n0 & 511;
    const float* xb  = x + (size_t)t * 768 * 512 + v0;
    const float* scb = g_scale + t * 768;
    const float* shb = g_shift + t * 768;

    float acc[8][8];
    #pragma unroll
    for (int i = 0; i < 8; i++)
        #pragma unroll
        for (int j = 0; j < 8; j++) acc[i][j] = 0.f;

    const int a_c = tid >> 5;          // 0..7
    const int a_v = (tid & 31) << 2;   // 0..124
    const int b_o = tid >> 2;          // 0..63
    const int b_k = (tid & 3) << 2;    // 0..12

    for (int k0 = 0; k0 < 768; k0 += 16) {
        #pragma unroll
        for (int r = 0; r < 2; r++) {
            int c = k0 + a_c + r * 8;
            float4 a = *(const float4*)(xb + (size_t)c * 512 + a_v);
            float sc = scb[c], sh = shb[c];
            a.x = fmaf(a.x, sc, sh);
            a.y = fmaf(a.y, sc, sh);
            a.z = fmaf(a.z, sc, sh);
            a.w = fmaf(a.w, sc, sh);
            *(float4*)(As + (a_c + r * 8) * 128 + a_v) = a;
        }
        #pragma unroll
        for (int r = 0; r < 2; r++) {
            int oo = o0 + b_o + r * 64;
            float4 b = *(const float4*)(w_in + (size_t)oo * 768 + k0 + b_k);
            Bs[(b_k + 0) * 128 + b_o + r * 64] = b.x;
            Bs[(b_k + 1) * 128 + b_o + r * 64] = b.y;
            Bs[(b_k + 2) * 128 + b_o + r * 64] = b.z;
            Bs[(b_k + 3) * 128 + b_o + r * 64] = b.w;
        }
        __syncthreads();
        #pragma unroll
        for (int kk = 0; kk < 16; kk++) {
            float ar[8], br[8];
            *(float4*)&ar[0] = *(float4*)(As + kk * 128 + tx * 4);
            *(float4*)&ar[4] = *(float4*)(As + kk * 128 + tx * 4 + 64);
            *(float4*)&br[0] = *(float4*)(Bs + kk * 128 + ty * 4);
            *(float4*)&br[4] = *(float4*)(Bs + kk * 128 + ty * 4 + 64);
            #pragma unroll
            for (int i = 0; i < 8; i++)
                #pragma unroll
                for (int j = 0; j < 8; j++)
                    acc[i][j] = fmaf(ar[i], br[j], acc[i][j]);
        }
        __syncthreads();
    }

    #pragma unroll
    for (int i = 0; i < 8; i++) {
        int n = n0 + tx * 4 + (i & 3) + (i >> 2) * 64;
        int tt = n >> 9, v = n & 511;
        #pragma unroll
        for (int jg = 0; jg < 2; jg++) {
            int o = o0 + ty * 4 + jg * 64;
            float4 val;
            val.x = acc[i][jg * 4 + 0] + b_in[o + 0];
            val.y = acc[i][jg * 4 + 1] + b_in[o + 1];
            val.z = acc[i][jg * 4 + 2] + b_in[o + 2];
            val.w = acc[i][jg * 4 + 3] + b_in[o + 3];
            int he = o / 192;
            int jj = o - he * 192;
            int part = jj >> 6;
            int c = jj & 63;
            float* dst = part == 0 ? g_q : (part == 1 ? g_k : g_v);
            *(float4*)(dst + (((size_t)v * 12 + he) * 64 + tt) * 64 + c) = val;
        }
    }
}

// ---------------------------------------------------------------------------
// 4) LayerNorm over hd=64 for q and k (rows contiguous), one warp per row.
// ---------------------------------------------------------------------------
__global__ void ln_qk_kernel(const float* __restrict__ qw, const float* __restrict__ qb2,
                             const float* __restrict__ kw, const float* __restrict__ kb2) {
    const int lane = threadIdx.x & 31;
    const int row = blockIdx.x * 8 + (threadIdx.x >> 5);
    #pragma unroll
    for (int which = 0; which < 2; which++) {
        float* p = (which == 0 ? g_q : g_k) + (size_t)row * 64;
        const float* wv = which == 0 ? qw : kw;
        const float* bv = which == 0 ? qb2 : kb2;
        float x0 = p[lane], x1 = p[lane + 32];
        float s = x0 + x1;
        #pragma unroll
        for (int o = 16; o; o >>= 1) s += __shfl_xor_sync(0xffffffffu, s, o);
        float mu = s * (1.f / 64.f);
        float d0 = x0 - mu, d1 = x1 - mu;
        float vv = d0 * d0 + d1 * d1;
        #pragma unroll
        for (int o = 16; o; o >>= 1) vv += __shfl_xor_sync(0xffffffffu, vv, o);
        float inv = rsqrtf(vv * (1.f / 64.f) + 1e-5f);
        p[lane]      = d0 * inv * wv[lane] + bv[lane];
        p[lane + 32] = d1 * inv * wv[lane + 32] + bv[lane + 32];
    }
}

// ---------------------------------------------------------------------------
// 5) Attention: one block per (v, he). scores = qk^T/8 + bias, softmax, @v.
//    smem: sqv holds q then v; skp holds k (pitch 65) then p (pitch 64).
// ---------------------------------------------------------------------------
__global__ void __launch_bounds__(256) attn_kernel() {
    __shared__ float sqv[64 * 64];
    __shared__ float skp[64 * 65];
    const int tid = threadIdx.x;
    const int blk = blockIdx.x;     // v*12 + he
    const int he = blk % 12;
    const int v  = blk / 12;
    const float* qb = g_q + (size_t)blk * 4096;
    const float* kb = g_k + (size_t)blk * 4096;

    #pragma unroll
    for (int it = 0; it < 4; it++) {
        int i = tid * 4 + it * 1024;
        *(float4*)(sqv + i) = *(const float4*)(qb + i);
        float4 kv = *(const float4*)(kb + i);
        int s = i >> 6, c = i & 63;
        float* kd = skp + s * 65 + c;
        kd[0] = kv.x; kd[1] = kv.y; kd[2] = kv.z; kd[3] = kv.w;
    }
    __syncthreads();

    const int tx = tid & 15, ty = tid >> 4;
    const int t0 = ty * 4, s0 = tx * 4;
    float acc[4][4];
    #pragma unroll
    for (int i = 0; i < 4; i++)
        #pragma unroll
        for (int j = 0; j < 4; j++) acc[i][j] = 0.f;

    #pragma unroll 4
    for (int c = 0; c < 64; c++) {
        float a[4], b[4];
        #pragma unroll
        for (int i = 0; i < 4; i++) a[i] = sqv[(t0 + i) * 64 + c];
        #pragma unroll
        for (int j = 0; j < 4; j++) b[j] = skp[(s0 + j) * 65 + c];
        #pragma unroll
        for (int i = 0; i < 4; i++)
            #pragma unroll
            for (int j = 0; j < 4; j++)
                acc[i][j] = fmaf(a[i], b[j], acc[i][j]);
    }
    __syncthreads();

    // p = acc/8 + bias  -> overwrite skp (pitch 64, k is dead)
    const float* bb = g_bias + he * 4096;
    #pragma unroll
    for (int i = 0; i < 4; i++) {
        float4 bi = *(const float4*)(bb + (t0 + i) * 64 + s0);
        float4 pv;
        pv.x = fmaf(acc[i][0], 0.125f, bi.x);
        pv.y = fmaf(acc[i][1], 0.125f, bi.y);
        pv.z = fmaf(acc[i][2], 0.125f, bi.z);
        pv.w = fmaf(acc[i][3], 0.125f, bi.w);
        *(float4*)(skp + (t0 + i) * 64 + s0) = pv;
    }
    __syncthreads();

    // load v into sqv (q is dead)
    const float* vb = g_v + (size_t)blk * 4096;
    #pragma unroll
    for (int it = 0; it < 4; it++) {
        int i = tid * 4 + it * 1024;
        *(float4*)(sqv + i) = *(const float4*)(vb + i);
    }

    // softmax: 4 threads per row (lanes tid&3 cooperate via shfl)
    {
        int r = tid >> 2, q = tid & 3;
        float* row = skp + r * 64;
        float mx = -1e30f;
        #pragma unroll
        for (int k = 0; k < 16; k++) mx = fmaxf(mx, row[q * 16 + k]);
        mx = fmaxf(mx, __shfl_xor_sync(0xffffffffu, mx, 1));
        mx = fmaxf(mx, __shfl_xor_sync(0xffffffffu, mx, 2));
        float e[16];
        float sum = 0.f;
        #pragma unroll
        for (int k = 0; k < 16; k++) {
            e[k] = expf(row[q * 16 + k] - mx);
            sum += e[k];
        }
        sum += __shfl_xor_sync(0xffffffffu, sum, 1);
        sum += __shfl_xor_sync(0xffffffffu, sum, 2);
        float rs = 1.f / sum;
        #pragma unroll
        for (int k = 0; k < 16; k++) row[q * 16 + k] = e[k] * rs;
    }
    __syncthreads();

    // O = P @ V ; thread = (t-group ty, c-group tx)
    float oacc[4][4];
    #pragma unroll
    for (int i = 0; i < 4; i++)
        #pragma unroll
        for (int j = 0; j < 4; j++) oacc[i][j] = 0.f;

    #pragma unroll 4
    for (int s = 0; s < 64; s++) {
        float4 vv = *(const float4*)(sqv + s * 64 + tx * 4);
        #pragma unroll
        for (int i = 0; i < 4; i++) {
            float p = skp[(t0 + i) * 64 + s];
            oacc[i][0] = fmaf(p, vv.x, oacc[i][0]);
            oacc[i][1] = fmaf(p, vv.y, oacc[i][1]);
            oacc[i][2] = fmaf(p, vv.z, oacc[i][2]);
            oacc[i][3] = fmaf(p, vv.w, oacc[i][3]);
        }
    }
    #pragma unroll
    for (int i = 0; i < 4; i++) {
        int tt = t0 + i;
        float4 ov = make_float4(oacc[i][0], oacc[i][1], oacc[i][2], oacc[i][3]);
        *(float4*)(g_o + ((size_t)(tt * 512 + v)) * 768 + he * 64 + tx * 4) = ov;
    }
}

// ---------------------------------------------------------------------------
// 6) GEMM2: out[t,oc,v] = x + gamma[oc] * (sum_c o[n,c]*w_out[oc,c] + b_out[oc])
// ---------------------------------------------------------------------------
__global__ void __launch_bounds__(256) gemm_out_kernel(
        const float* __restrict__ x,
        const float* __restrict__ w_out,
        const float* __restrict__ b_out,
        const float* __restrict__ gamma,
        float* __restrict__ out) {
    __shared__ float As[16 * 128];
    __shared__ float Bs[16 * 128];
    const int tid = threadIdx.x;
    const int tx = tid & 15, ty = tid >> 4;
    const int n0 = blockIdx.y * 128;
    const int o0 = blockIdx.x * 128;

    float acc[8][8];
    #pragma unroll
    for (int i = 0; i < 8; i++)
        #pragma unroll
        for (int j = 0; j < 8; j++) acc[i][j] = 0.f;

    const int l_r = tid >> 2;
    const int l_k = (tid & 3) << 2;

    for (int k0 = 0; k0 < 768; k0 += 16) {
        #pragma unroll
        for (int r = 0; r < 2; r++) {
            int m = l_r + r * 64;
            float4 a = *(const float4*)(g_o + (size_t)(n0 + m) * 768 + k0 + l_k);
            As[(l_k + 0) * 128 + m] = a.x;
            As[(l_k + 1) * 128 + m] = a.y;
            As[(l_k + 2) * 128 + m] = a.z;
            As[(l_k + 3) * 128 + m] = a.w;
            float4 b = *(const float4*)(w_out + (size_t)(o0 + m) * 768 + k0 + l_k);
            Bs[(l_k + 0) * 128 + m] = b.x;
            Bs[(l_k + 1) * 128 + m] = b.y;
            Bs[(l_k + 2) * 128 + m] = b.z;
            Bs[(l_k + 3) * 128 + m] = b.w;
        }
        __syncthreads();
        #pragma unroll
        for (int kk = 0; kk < 16; kk++) {
            float ar[8], br[8];
            *(float4*)&ar[0] = *(float4*)(As + kk * 128 + tx * 4);
            *(float4*)&ar[4] = *(float4*)(As + kk * 128 + tx * 4 + 64);
            *(float4*)&br[0] = *(float4*)(Bs + kk * 128 + ty * 4);
            *(float4*)&br[4] = *(float4*)(Bs + kk * 128 + ty * 4 + 64);
            #pragma unroll
            for (int i = 0; i < 8; i++)
                #pragma unroll
                for (int j = 0; j < 8; j++)
                    acc[i][j] = fmaf(ar[i], br[j], acc[i][j]);
        }
        __syncthreads();
    }

    #pragma unroll
    for (int i = 0; i < 8; i++) {
        int n = n0 + tx * 4 + (i & 3) + (i >> 2) * 64;
        int tt = n >> 9, v = n & 511;
        int base = tt * 393216 + v;
        #pragma unroll
        for (int j = 0; j < 8; j++) {
            int oc = o0 + ty * 4 + (j & 3) + (j >> 2) * 64;
            int addr = base + oc * 512;
            out[addr] = x[addr] + gamma[oc] * (acc[i][j] + b_out[oc]);
        }
    }
}

// ---------------------------------------------------------------------------
extern "C" void kernel_launch(void* const* d_in, const int* in_sizes, int n_in,
                              void* d_out, int out_size) {
    const float* x      = (const float*)d_in[0];
    const float* norm1w = (const float*)d_in[1];
    const float* w_in   = (const float*)d_in[2];
    const float* b_in   = (const float*)d_in[3];
    const float* qn_w   = (const float*)d_in[4];
    const float* qn_b   = (const float*)d_in[5];
    const float* kn_w   = (const float*)d_in[6];
    const float* kn_b   = (const float*)d_in[7];
    const float* rel    = (const float*)d_in[8];
    const float* w_out  = (const float*)d_in[9];
    const float* b_out  = (const float*)d_in[10];
    const float* gamma  = (const float*)d_in[11];
    float* out = (float*)d_out;

    gn_stats_kernel<<<768, 256>>>(x, norm1w);
    bias_kernel<<<64, 64>>>(rel);
    gemm_qkv_kernel<<<dim3(18, 256), 256>>>(x, w_in, b_in);
    ln_qk_kernel<<<49152, 256>>>(qn_w, qn_b, kn_w, kn_b);
    attn_kernel<<<6144, 256>>>();
    gemm_out_kernel<<<dim3(6, 256), 256>>>(x, w_out, b_out, gamma, out);
}